// round 15
// baseline (speedup 1.0000x reference)
#include <cuda_runtime.h>
#include <cuda_bf16.h>
#include <math.h>
#include <stdint.h>

// Problem constants
#define B_   8
#define T_   1024
#define C_   256
#define H_   16
#define D_   16
#define M_   (B_ * T_)        // 8192
#define FF_  (4 * C_)         // 1024
#define EPS_ 1e-5f
#define QSCALE_ 0.360673760222f   // 0.25 * log2(e)

#define NBLOCKS 296

// ---------------- scratch ----------------
__device__ __nv_bfloat16 g_h1b [M_ * C_];
__device__ __nv_bfloat16 g_attb[M_ * C_];
__device__ __nv_bfloat16 g_h2b [M_ * C_];
__device__ __nv_bfloat16 g_h3b [M_ * FF_];
__device__ __nv_bfloat16 g_qkvb[M_ * 3 * C_];
__device__ float         g_x2  [M_ * C_];
__device__ __nv_bfloat16 g_wqkvt[3 * C_ * C_];
__device__ __nv_bfloat16 g_wpt  [C_ * C_];
__device__ __nv_bfloat16 g_w1t  [FF_ * C_];
__device__ __nv_bfloat16 g_w2t  [C_ * FF_];

// ---------------- grid barrier state ----------------
__device__ int g_bar_count;   // zero-init
__device__ int g_bar_epoch;   // zero-init

__device__ __forceinline__ void grid_sync()
{
    __syncthreads();
    if (threadIdx.x == 0) {
        volatile int* vcount = &g_bar_count;
        volatile int* vepoch = &g_bar_epoch;
        __threadfence();
        int e = *vepoch;
        if (atomicAdd(&g_bar_count, 1) == (int)gridDim.x - 1) {
            *vcount = 0;
            __threadfence();
            *vepoch = e + 1;
        } else {
            while (*vepoch == e) { __nanosleep(64); }
        }
        __threadfence();
    }
    __syncthreads();
}

__device__ __forceinline__ uint32_t smem_u32(const void* p) {
    uint32_t a;
    asm("{ .reg .u64 t; cvta.to.shared.u64 t, %1; cvt.u32.u64 %0, t; }" : "=r"(a) : "l"(p));
    return a;
}
__device__ __forceinline__ float ex2f(float x) {
    float y;
    asm("ex2.approx.ftz.f32 %0, %1;" : "=f"(y) : "f"(x));
    return y;
}
#define CP_ASYNC16(dst, src) \
    asm volatile("cp.async.cg.shared.global [%0], [%1], 16;" :: "r"(dst), "l"(src))
#define CP_COMMIT() asm volatile("cp.async.commit_group;" ::: "memory")
#define CP_WAIT(n)  asm volatile("cp.async.wait_group %0;" :: "n"(n) : "memory")
#define NBAR(id) asm volatile("bar.sync %0, 128;" :: "r"(id) : "memory")

// ---------------- LN row (device) ----------------
__device__ __forceinline__ void ln_row(const float* __restrict__ x, const float* __restrict__ g,
                                       const float* __restrict__ b, __nv_bfloat16* __restrict__ y,
                                       int row, int lane)
{
    const float* xr = x + (size_t)row * C_;
    float v[8], s = 0.f;
#pragma unroll
    for (int i = 0; i < 8; i++) { v[i] = xr[lane + 32 * i]; s += v[i]; }
#pragma unroll
    for (int o = 16; o > 0; o >>= 1) s += __shfl_xor_sync(0xffffffffu, s, o);
    float mu = s * (1.f / C_);
    float var = 0.f;
#pragma unroll
    for (int i = 0; i < 8; i++) { float d = v[i] - mu; var += d * d; }
#pragma unroll
    for (int o = 16; o > 0; o >>= 1) var += __shfl_xor_sync(0xffffffffu, var, o);
    float rstd = rsqrtf(var * (1.f / C_) + EPS_);
    __nv_bfloat16* yr = y + (size_t)row * C_;
#pragma unroll
    for (int i = 0; i < 8; i++) {
        int c = lane + 32 * i;
        yr[c] = __float2bfloat16((v[i] - mu) * rstd * g[c] + b[c]);
    }
}

// ---------------- phase 0: weight transposes + ln1 ----------------
__device__ __forceinline__ void prep_phase(
    const float* Wq, const float* Wk, const float* Wv, const float* Wp,
    const float* W1, const float* W2,
    const float* x, const float* g1, const float* be1, char* dsm)
{
    const int tid = threadIdx.x;
    float (*t)[33] = (float(*)[33])dsm;   // 32x33 fp32 = 4224 B

    for (int bid = blockIdx.x; bid < 1792; bid += gridDim.x) {
        __syncthreads();
        if (bid >= 768) {
            int row = (bid - 768) * 8 + (tid >> 5);
            ln_row(x, g1, be1, g_h1b, row, tid & 31);
            continue;
        }
        const float* in; __nv_bfloat16* out; int K, N, tt;
        if (bid < 192)       { int w = bid >> 6; tt = bid & 63;
                               in = (w == 0) ? Wq : (w == 1) ? Wk : Wv;
                               out = g_wqkvt + w * C_ * C_; K = C_; N = C_; }
        else if (bid < 256)  { tt = bid - 192; in = Wp; out = g_wpt; K = C_;  N = C_;  }
        else if (bid < 512)  { tt = bid - 256; in = W1; out = g_w1t; K = C_;  N = FF_; }
        else                 { tt = bid - 512; in = W2; out = g_w2t; K = FF_; N = C_;  }
        int ntx = N >> 5;
        int n0 = (tt % ntx) * 32, k0 = (tt / ntx) * 32;
        int tx = tid & 31, ty = tid >> 5;
#pragma unroll
        for (int i = ty; i < 32; i += 8)
            t[i][tx] = in[(size_t)(k0 + i) * N + n0 + tx];
        __syncthreads();
#pragma unroll
        for (int i = ty; i < 32; i += 8)
            out[(size_t)(n0 + i) * K + k0 + tx] = __float2bfloat16(t[tx][i]);
    }
}

// ---------------- GEMM phase: 64x128 tile, BK=64, 3-stage pipeline ----------------
#define GF_BIAS 1
#define GF_RELU 2
#define GF_RES  4
#define BM 64
#define BN 128
#define BK 64
#define PITCH 72
#define STG 3
#define A_BYTES (BM * PITCH * 2)              // 9216
#define STAGE_BYTES ((BM + BN) * PITCH * 2)   // 27648
#define GEMM_DSM (STG * STAGE_BYTES)          // 82944

__device__ __forceinline__ void gemm_phase(
    const __nv_bfloat16* __restrict__ A, const __nv_bfloat16* __restrict__ Bt,
    const float* __restrict__ bias, const float* __restrict__ res,
    float* __restrict__ outf, __nv_bfloat16* __restrict__ outb,
    int N, int K, int flags, int ntiles, int nbx, char* dsm)
{
    const int tid  = threadIdx.x;
    const int wid  = tid >> 5;
    const int lane = tid & 31;
    const int warp_m = wid >> 2;
    const int warp_n = wid & 3;
    const uint32_t sbase = smem_u32(dsm);
    const int a_row0 = tid >> 3;
    const int a_c8   = (tid & 7) << 3;
    const int nch = K / BK;

    for (int tile = blockIdx.x; tile < ntiles; tile += gridDim.x) {
        const int row0 = (tile / nbx) * BM;
        const int col0 = (tile % nbx) * BN;
        __syncthreads();   // previous tile's smem reads complete

        float acc[2][4][4];
#pragma unroll
        for (int i = 0; i < 2; i++)
#pragma unroll
            for (int j = 0; j < 4; j++)
#pragma unroll
                for (int r = 0; r < 4; r++) acc[i][j][r] = 0.f;

#pragma unroll
        for (int p = 0; p < 2; p++) {
            int k0 = p * BK;
            uint32_t baseA = sbase + (uint32_t)(p * STAGE_BYTES);
            uint32_t baseB = baseA + A_BYTES;
#pragma unroll
            for (int v = 0; v < 2; v++) {
                int row = a_row0 + v * 32;
                CP_ASYNC16(baseA + (uint32_t)(row * PITCH + a_c8) * 2,
                           A + (size_t)(row0 + row) * K + k0 + a_c8);
            }
#pragma unroll
            for (int v = 0; v < 4; v++) {
                int row = a_row0 + v * 32;
                CP_ASYNC16(baseB + (uint32_t)(row * PITCH + a_c8) * 2,
                           Bt + (size_t)(col0 + row) * K + k0 + a_c8);
            }
            CP_COMMIT();
        }

        for (int ch = 0; ch < nch; ch++) {
            if (ch + 1 < nch) { CP_WAIT(1); } else { CP_WAIT(0); }
            __syncthreads();

            if (ch + 2 < nch) {
                int k0 = (ch + 2) * BK;
                int nb = (ch + 2) % STG;
                uint32_t baseA = sbase + (uint32_t)(nb * STAGE_BYTES);
                uint32_t baseB = baseA + A_BYTES;
#pragma unroll
                for (int v = 0; v < 2; v++) {
                    int row = a_row0 + v * 32;
                    CP_ASYNC16(baseA + (uint32_t)(row * PITCH + a_c8) * 2,
                               A + (size_t)(row0 + row) * K + k0 + a_c8);
                }
#pragma unroll
                for (int v = 0; v < 4; v++) {
                    int row = a_row0 + v * 32;
                    CP_ASYNC16(baseB + (uint32_t)(row * PITCH + a_c8) * 2,
                               Bt + (size_t)(col0 + row) * K + k0 + a_c8);
                }
                CP_COMMIT();
            }

            int buf = ch % STG;
            uint32_t aBase = sbase + (uint32_t)(buf * STAGE_BYTES);
            uint32_t bBase = aBase + A_BYTES;

#pragma unroll
            for (int kk = 0; kk < 4; kk++) {
                uint32_t a[2][4], b[4][2];
#pragma unroll
                for (int i = 0; i < 2; i++) {
                    int r = warp_m * 32 + i * 16 + (lane & 15);
                    int c = kk * 16 + ((lane >> 4) << 3);
                    uint32_t addr = aBase + (uint32_t)(r * PITCH + c) * 2;
                    asm volatile("ldmatrix.sync.aligned.m8n8.x4.shared.b16 {%0,%1,%2,%3}, [%4];"
                                 : "=r"(a[i][0]), "=r"(a[i][1]), "=r"(a[i][2]), "=r"(a[i][3])
                                 : "r"(addr));
                }
#pragma unroll
                for (int j = 0; j < 4; j++) {
                    int r = warp_n * 32 + j * 8 + (lane & 7);
                    int c = kk * 16 + (((lane >> 3) & 1) << 3);
                    uint32_t addr = bBase + (uint32_t)(r * PITCH + c) * 2;
                    asm volatile("ldmatrix.sync.aligned.m8n8.x2.shared.b16 {%0,%1}, [%2];"
                                 : "=r"(b[j][0]), "=r"(b[j][1]) : "r"(addr));
                }
#pragma unroll
                for (int i = 0; i < 2; i++)
#pragma unroll
                    for (int j = 0; j < 4; j++) {
                        asm volatile(
                            "mma.sync.aligned.m16n8k16.row.col.f32.bf16.bf16.f32 "
                            "{%0,%1,%2,%3}, {%4,%5,%6,%7}, {%8,%9}, {%0,%1,%2,%3};"
                            : "+f"(acc[i][j][0]), "+f"(acc[i][j][1]),
                              "+f"(acc[i][j][2]), "+f"(acc[i][j][3])
                            : "r"(a[i][0]), "r"(a[i][1]), "r"(a[i][2]), "r"(a[i][3]),
                              "r"(b[j][0]), "r"(b[j][1]));
                    }
            }
        }

        const int qr = lane >> 2;
        const int qc = (lane & 3) * 2;
#pragma unroll
        for (int i = 0; i < 2; i++) {
#pragma unroll
            for (int j = 0; j < 4; j++) {
                int gc = col0 + warp_n * 32 + j * 8 + qc;
#pragma unroll
                for (int half = 0; half < 2; half++) {
                    int gr = row0 + warp_m * 32 + i * 16 + qr + half * 8;
                    float v0 = acc[i][j][half * 2 + 0];
                    float v1 = acc[i][j][half * 2 + 1];
                    if (flags & GF_BIAS) { v0 += bias[gc]; v1 += bias[gc + 1]; }
                    if (flags & GF_RES) {
                        const float* rp = res + (size_t)gr * N + gc;
                        v0 += rp[0]; v1 += rp[1];
                    }
                    if (flags & GF_RELU) { v0 = fmaxf(v0, 0.f); v1 = fmaxf(v1, 0.f); }
                    if (outf) *(float2*)(outf + (size_t)gr * N + gc) = make_float2(v0, v1);
                    if (outb) {
                        __nv_bfloat162 p = __floats2bfloat162_rn(v0, v1);
                        *(__nv_bfloat162*)(outb + (size_t)gr * N + gc) = p;
                    }
                }
            }
        }
    }
}

// ---------------- fattn phase: 2 q-tiles per block (named barriers per half) ----------------
#define APITCH 24
#define FA_HALF_BYTES 15360    // Qs 3072 + Ks 2x3072 + Vs 2x3072

__device__ __forceinline__ void fattn_phase(
    const __nv_bfloat16* __restrict__ qkv, __nv_bfloat16* __restrict__ out, char* dsm)
{
    const int tid  = threadIdx.x;
    const int htid = tid & 127;
    const int half = tid >> 7;
    char* my = dsm + half * FA_HALF_BYTES;
    __nv_bfloat16* Qs  = (__nv_bfloat16*)(my);
    __nv_bfloat16* KsB = (__nv_bfloat16*)(my + 3072);
    __nv_bfloat16* VsB = (__nv_bfloat16*)(my + 9216);

    const int wm = htid >> 5, lane = tid & 31;
    const int g = lane >> 2, tig = lane & 3;
    const int LD = 3 * C_;
    const int l_row = htid >> 1, l_half = htid & 1;
    const int barid = half + 1;

    // ones column (cols 16..23) in both V buffers; never overwritten by cp.async
    {
        const uint4 ones_vec = make_uint4(0x00003F80u, 0u, 0u, 0u);
        *(uint4*)&VsB[l_half * (64 * APITCH) + l_row * APITCH + 16] = ones_vec;
    }

    for (int u = blockIdx.x; u < 1024; u += gridDim.x) {
        int tile = u * 2 + half;
        int qb = tile & 15;
        int bh = tile >> 4;            // 0..127
        int b  = bh >> 4, h = bh & 15;
        const size_t base = (size_t)b * T_ * LD;

        NBAR(barid);   // previous tile of this half fully done

        // Q load + scale
        {
            const __nv_bfloat16* src = qkv + base + (size_t)(qb * 64 + l_row) * LD + h * D_ + l_half * 8;
            uint4 uu = *(const uint4*)src;
            __nv_bfloat16 tmp[8]; *(uint4*)&tmp[0] = uu;
#pragma unroll
            for (int i = 0; i < 8; i++)
                Qs[l_row * APITCH + l_half * 8 + i] =
                    __float2bfloat16(__bfloat162float(tmp[i]) * QSCALE_);
        }
        // prologue: K/V kt=0
        {
            const __nv_bfloat16* ksrc = qkv + base + (size_t)l_row * LD + C_ + h * D_ + l_half * 8;
            CP_ASYNC16(smem_u32(&KsB[l_row * APITCH + l_half * 8]), ksrc);
            CP_ASYNC16(smem_u32(&VsB[l_row * APITCH + l_half * 8]), ksrc + C_);
            CP_COMMIT();
        }
        NBAR(barid);

        uint32_t qa[4];
        {
            int r = wm * 16 + (lane & 15);
            int c = (lane >> 4) << 3;
            uint32_t addr = smem_u32(&Qs[r * APITCH + c]);
            asm volatile("ldmatrix.sync.aligned.m8n8.x4.shared.b16 {%0,%1,%2,%3}, [%4];"
                         : "=r"(qa[0]), "=r"(qa[1]), "=r"(qa[2]), "=r"(qa[3]) : "r"(addr));
        }

        float o[3][4];
#pragma unroll
        for (int n = 0; n < 3; n++)
#pragma unroll
            for (int r = 0; r < 4; r++) o[n][r] = 0.f;

        for (int kt = 0; kt <= qb; kt++) {
            CP_WAIT(0);
            NBAR(barid);

            if (kt < qb) {
                const __nv_bfloat16* ksrc = qkv + base + (size_t)((kt + 1) * 64 + l_row) * LD + C_ + h * D_ + l_half * 8;
                int nb = (kt + 1) & 1;
                CP_ASYNC16(smem_u32(&KsB[nb * (64 * APITCH) + l_row * APITCH + l_half * 8]), ksrc);
                CP_ASYNC16(smem_u32(&VsB[nb * (64 * APITCH) + l_row * APITCH + l_half * 8]), ksrc + C_);
                CP_COMMIT();
            }

            const __nv_bfloat16* Kb = KsB + (kt & 1) * (64 * APITCH);
            const __nv_bfloat16* Vb = VsB + (kt & 1) * (64 * APITCH);

            float s[8][4];
#pragma unroll
            for (int f = 0; f < 8; f++) {
                uint32_t b0, b1;
                int r = f * 8 + (lane & 7);
                int c = ((lane >> 3) & 1) << 3;
                uint32_t addr = smem_u32(&Kb[r * APITCH + c]);
                asm volatile("ldmatrix.sync.aligned.m8n8.x2.shared.b16 {%0,%1}, [%2];"
                             : "=r"(b0), "=r"(b1) : "r"(addr));
                s[f][0] = s[f][1] = s[f][2] = s[f][3] = 0.f;
                asm volatile(
                    "mma.sync.aligned.m16n8k16.row.col.f32.bf16.bf16.f32 "
                    "{%0,%1,%2,%3}, {%4,%5,%6,%7}, {%8,%9}, {%0,%1,%2,%3};"
                    : "+f"(s[f][0]), "+f"(s[f][1]), "+f"(s[f][2]), "+f"(s[f][3])
                    : "r"(qa[0]), "r"(qa[1]), "r"(qa[2]), "r"(qa[3]), "r"(b0), "r"(b1));
            }

            if (kt == qb) {
                int q0 = wm * 16 + g, q1 = q0 + 8;
#pragma unroll
                for (int f = 0; f < 8; f++) {
                    int k0 = f * 8 + 2 * tig;
                    if (k0     > q0) s[f][0] = -1e30f;
                    if (k0 + 1 > q0) s[f][1] = -1e30f;
                    if (k0     > q1) s[f][2] = -1e30f;
                    if (k0 + 1 > q1) s[f][3] = -1e30f;
                }
            }

            uint32_t pa[8][2];
#pragma unroll
            for (int f = 0; f < 8; f++) {
                float p0 = ex2f(s[f][0]), p1 = ex2f(s[f][1]);
                float p2 = ex2f(s[f][2]), p3 = ex2f(s[f][3]);
                __nv_bfloat162 uu = __floats2bfloat162_rn(p0, p1);
                __nv_bfloat162 ww = __floats2bfloat162_rn(p2, p3);
                pa[f][0] = *(uint32_t*)&uu;
                pa[f][1] = *(uint32_t*)&ww;
            }

#pragma unroll
            for (int j2 = 0; j2 < 4; j2++) {
                int vr = j2 * 16 + (lane & 15);
#pragma unroll
                for (int n = 0; n < 3; n++) {
                    uint32_t b0, b1;
                    uint32_t addr = smem_u32(&Vb[vr * APITCH + n * 8]);
                    asm volatile("ldmatrix.sync.aligned.m8n8.x2.trans.shared.b16 {%0,%1}, [%2];"
                                 : "=r"(b0), "=r"(b1) : "r"(addr));
                    asm volatile(
                        "mma.sync.aligned.m16n8k16.row.col.f32.bf16.bf16.f32 "
                        "{%0,%1,%2,%3}, {%4,%5,%6,%7}, {%8,%9}, {%0,%1,%2,%3};"
                        : "+f"(o[n][0]), "+f"(o[n][1]), "+f"(o[n][2]), "+f"(o[n][3])
                        : "r"(pa[2*j2][0]), "r"(pa[2*j2][1]),
                          "r"(pa[2*j2+1][0]), "r"(pa[2*j2+1][1]),
                          "r"(b0), "r"(b1));
                }
            }
        }

        float l0 = __shfl_sync(0xffffffffu, o[2][0], lane & ~3);
        float l1 = __shfl_sync(0xffffffffu, o[2][2], lane & ~3);
        float inv0 = 1.f / l0, inv1 = 1.f / l1;

        int gr0 = qb * 64 + wm * 16 + g;
        int gr1 = gr0 + 8;
#pragma unroll
        for (int n = 0; n < 2; n++) {
            int gc = h * D_ + n * 8 + 2 * tig;
            __nv_bfloat162 p0 = __floats2bfloat162_rn(o[n][0] * inv0, o[n][1] * inv0);
            __nv_bfloat162 p1 = __floats2bfloat162_rn(o[n][2] * inv1, o[n][3] * inv1);
            *(__nv_bfloat162*)(out + (size_t)(b * T_ + gr0) * C_ + gc) = p0;
            *(__nv_bfloat162*)(out + (size_t)(b * T_ + gr1) * C_ + gc) = p1;
        }
    }
}

// ---------------- the megakernel ----------------
__global__ __launch_bounds__(256, 2) void megakernel(
    const float* __restrict__ x,
    const float* __restrict__ Wq, const float* __restrict__ Wk,
    const float* __restrict__ Wv, const float* __restrict__ Wp,
    const float* __restrict__ bp,
    const float* __restrict__ W1, const float* __restrict__ b1,
    const float* __restrict__ W2, const float* __restrict__ b2,
    const float* __restrict__ g1, const float* __restrict__ be1,
    const float* __restrict__ g2, const float* __restrict__ be2,
    float* __restrict__ out)
{
    extern __shared__ __align__(16) char dsm[];
    const int tid = threadIdx.x;

    // phase 0: weight transposes + ln1
    prep_phase(Wq, Wk, Wv, Wp, W1, W2, x, g1, be1, dsm);
    grid_sync();

    // phase 1: qkv = h1 @ [Wq|Wk|Wv]^T
    gemm_phase(g_h1b, g_wqkvt, nullptr, nullptr, nullptr, g_qkvb,
               3 * C_, C_, 0, 768, 6, dsm);
    grid_sync();

    // phase 2: flash attention
    fattn_phase(g_qkvb, g_attb, dsm);
    grid_sync();

    // phase 3: x2 = x + att @ Wp^T + bp
    gemm_phase(g_attb, g_wpt, bp, x, g_x2, nullptr,
               C_, C_, GF_BIAS | GF_RES, 256, 2, dsm);
    grid_sync();

    // phase 4: ln2
    for (int u = blockIdx.x; u < M_ / 8; u += gridDim.x) {
        int row = u * 8 + (tid >> 5);
        ln_row(g_x2, g2, be2, g_h2b, row, tid & 31);
    }
    grid_sync();

    // phase 5: h3 = relu(h2 @ W1^T + b1)
    gemm_phase(g_h2b, g_w1t, b1, nullptr, nullptr, g_h3b,
               FF_, C_, GF_BIAS | GF_RELU, 1024, 8, dsm);
    grid_sync();

    // phase 6: out = x2 + h3 @ W2^T + b2
    gemm_phase(g_h3b, g_w2t, b2, g_x2, out, nullptr,
               C_, FF_, GF_BIAS | GF_RES, 256, 2, dsm);
}

// ---------------- host ----------------
extern "C" void kernel_launch(void* const* d_in, const int* in_sizes, int n_in,
                              void* d_out, int out_size)
{
    const float* x   = (const float*)d_in[0];
    const float* Wq  = (const float*)d_in[1];
    const float* Wk  = (const float*)d_in[2];
    const float* Wv  = (const float*)d_in[3];
    const float* Wp  = (const float*)d_in[4];
    const float* bp  = (const float*)d_in[5];
    const float* W1  = (const float*)d_in[6];
    const float* b1  = (const float*)d_in[7];
    const float* W2  = (const float*)d_in[8];
    const float* b2  = (const float*)d_in[9];
    const float* g1  = (const float*)d_in[10];
    const float* be1 = (const float*)d_in[11];
    const float* g2  = (const float*)d_in[12];
    const float* be2 = (const float*)d_in[13];
    float* out = (float*)d_out;

    cudaFuncSetAttribute(megakernel, cudaFuncAttributeMaxDynamicSharedMemorySize, GEMM_DSM);

    megakernel<<<NBLOCKS, 256, GEMM_DSM>>>(x, Wq, Wk, Wv, Wp, bp, W1, b1, W2, b2,
                                           g1, be1, g2, be2, out);
}

// round 16
// speedup vs baseline: 1.2190x; 1.2190x over previous
#include <cuda_runtime.h>
#include <cuda_bf16.h>
#include <math.h>
#include <stdint.h>

// Problem constants
#define B_   8
#define T_   1024
#define C_   256
#define H_   16
#define D_   16
#define M_   (B_ * T_)        // 8192
#define FF_  (4 * C_)         // 1024
#define EPS_ 1e-5f
#define QSCALE_ 0.360673760222f   // 0.25 * log2(e)

// ---------------- scratch ----------------
__device__ __nv_bfloat16 g_h1b [M_ * C_];
__device__ __nv_bfloat16 g_attb[M_ * C_];
__device__ __nv_bfloat16 g_h2b [M_ * C_];
__device__ __nv_bfloat16 g_h3b [M_ * FF_];
__device__ __nv_bfloat16 g_qkvb[M_ * 3 * C_];   // [row, 768]: q|k|v (bf16)
__device__ float         g_x2  [M_ * C_];
__device__ __nv_bfloat16 g_wqkvt[3 * C_ * C_];  // [768, 256]
__device__ __nv_bfloat16 g_wpt  [C_ * C_];
__device__ __nv_bfloat16 g_w1t  [FF_ * C_];
__device__ __nv_bfloat16 g_w2t  [C_ * FF_];

__device__ __forceinline__ uint32_t smem_u32(const void* p) {
    uint32_t a;
    asm("{ .reg .u64 t; cvta.to.shared.u64 t, %1; cvt.u32.u64 %0, t; }" : "=r"(a) : "l"(p));
    return a;
}
__device__ __forceinline__ float ex2f(float x) {
    float y;
    asm("ex2.approx.ftz.f32 %0, %1;" : "=f"(y) : "f"(x));
    return y;
}
#define CP_ASYNC16(dst, src) \
    asm volatile("cp.async.cg.shared.global [%0], [%1], 16;" :: "r"(dst), "l"(src))
#define CP_COMMIT() asm volatile("cp.async.commit_group;" ::: "memory")
#define CP_WAIT(n)  asm volatile("cp.async.wait_group %0;" :: "n"(n) : "memory")

// ---------------- LN body (device) ----------------
__device__ __forceinline__ void ln_row(const float* __restrict__ x, const float* __restrict__ g,
                                       const float* __restrict__ b, __nv_bfloat16* __restrict__ y,
                                       int row, int lane)
{
    const float* xr = x + (size_t)row * C_;
    float v[8], s = 0.f;
#pragma unroll
    for (int i = 0; i < 8; i++) { v[i] = xr[lane + 32 * i]; s += v[i]; }
#pragma unroll
    for (int o = 16; o > 0; o >>= 1) s += __shfl_xor_sync(0xffffffffu, s, o);
    float mu = s * (1.f / C_);
    float var = 0.f;
#pragma unroll
    for (int i = 0; i < 8; i++) { float d = v[i] - mu; var += d * d; }
#pragma unroll
    for (int o = 16; o > 0; o >>= 1) var += __shfl_xor_sync(0xffffffffu, var, o);
    float rstd = rsqrtf(var * (1.f / C_) + EPS_);
    __nv_bfloat16* yr = y + (size_t)row * C_;
#pragma unroll
    for (int i = 0; i < 8; i++) {
        int c = lane + 32 * i;
        yr[c] = __float2bfloat16((v[i] - mu) * rstd * g[c] + b[c]);
    }
}

__global__ void ln_kernel(const float* __restrict__ x, const float* __restrict__ g,
                          const float* __restrict__ b, __nv_bfloat16* __restrict__ y)
{
    int row  = blockIdx.x * 8 + (threadIdx.x >> 5);
    ln_row(x, g, b, y, row, threadIdx.x & 31);
}

// ---------------- prep: weight transposes + ln1, one launch ----------------
__global__ void prep_kernel(const float* __restrict__ Wq, const float* __restrict__ Wk,
                            const float* __restrict__ Wv, const float* __restrict__ Wp,
                            const float* __restrict__ W1, const float* __restrict__ W2,
                            __nv_bfloat16* __restrict__ wqkvt, __nv_bfloat16* __restrict__ wpt,
                            __nv_bfloat16* __restrict__ w1t, __nv_bfloat16* __restrict__ w2t,
                            const float* __restrict__ x, const float* __restrict__ g1,
                            const float* __restrict__ be1, __nv_bfloat16* __restrict__ h1b)
{
    int bid = blockIdx.x;
    if (bid >= 768) {
        int row = (bid - 768) * 8 + (threadIdx.x >> 5);
        ln_row(x, g1, be1, h1b, row, threadIdx.x & 31);
        return;
    }
    __shared__ float t[32][33];
    const float* in; __nv_bfloat16* out; int K, N, tt;
    if (bid < 192)       { int w = bid >> 6; tt = bid & 63;
                           in = (w == 0) ? Wq : (w == 1) ? Wk : Wv;
                           out = wqkvt + w * C_ * C_; K = C_; N = C_; }
    else if (bid < 256)  { tt = bid - 192; in = Wp; out = wpt; K = C_;  N = C_;  }
    else if (bid < 512)  { tt = bid - 256; in = W1; out = w1t; K = C_;  N = FF_; }
    else                 { tt = bid - 512; in = W2; out = w2t; K = FF_; N = C_;  }
    int ntx = N >> 5;
    int n0 = (tt % ntx) * 32, k0 = (tt / ntx) * 32;
    int tx = threadIdx.x & 31, ty = threadIdx.x >> 5;
#pragma unroll
    for (int i = ty; i < 32; i += 8)
        t[i][tx] = in[(size_t)(k0 + i) * N + n0 + tx];
    __syncthreads();
#pragma unroll
    for (int i = ty; i < 32; i += 8)
        out[(size_t)(n0 + i) * K + k0 + tx] = __float2bfloat16(t[tx][i]);
}

// ---------------- bf16 mma.sync GEMM, 3-stage pipeline, BK=64, 128x128 tile ----------------
// 512 threads (4x4 warps, 32x32 per warp), 1 block/SM, halved B re-read traffic.
#define GF_BIAS 1
#define GF_RELU 2
#define GF_RES  4
#define BM 128
#define BN 128
#define BK 64
#define PITCH 72                      // 64 + 8 pad bf16 per row
#define STG 3
#define A_BYTES (BM * PITCH * 2)              // 18432
#define STAGE_BYTES ((BM + BN) * PITCH * 2)   // 36864
#define GEMM_DSM (STG * STAGE_BYTES)          // 110592

__global__ __launch_bounds__(512) void mma_gemm(
    const __nv_bfloat16* __restrict__ A, const __nv_bfloat16* __restrict__ Bt,
    const float* __restrict__ bias, const float* __restrict__ res,
    float* __restrict__ outf, __nv_bfloat16* __restrict__ outb,
    int N, int K, int flags)
{
    extern __shared__ __align__(16) char dsm[];

    const int tid  = threadIdx.x;
    const int wid  = tid >> 5;
    const int lane = tid & 31;
    const int warp_m = wid >> 2;   // 0..3 -> 32 rows each
    const int warp_n = wid & 3;    // 0..3 -> 32 cols each
    const int row0 = blockIdx.y * BM;
    const int col0 = blockIdx.x * BN;

    const uint32_t sbase = smem_u32(dsm);

    // load mapping: A 1024 vec16 (2/thread), B 1024 vec16 (2/thread)
    const int a_row0 = tid >> 3;              // 0..63 (+64 for second)
    const int a_c8   = (tid & 7) << 3;        // 0..56

    float acc[2][4][4];
#pragma unroll
    for (int i = 0; i < 2; i++)
#pragma unroll
        for (int j = 0; j < 4; j++)
#pragma unroll
            for (int r = 0; r < 4; r++) acc[i][j][r] = 0.f;

    const int nch = K / BK;

    // prologue: issue chunks 0 and 1
#pragma unroll
    for (int p = 0; p < 2; p++) {
        int k0 = p * BK;
        uint32_t baseA = sbase + (uint32_t)(p * STAGE_BYTES);
        uint32_t baseB = baseA + A_BYTES;
#pragma unroll
        for (int v = 0; v < 2; v++) {
            int row = a_row0 + v * 64;
            CP_ASYNC16(baseA + (uint32_t)(row * PITCH + a_c8) * 2,
                       A + (size_t)(row0 + row) * K + k0 + a_c8);
            CP_ASYNC16(baseB + (uint32_t)(row * PITCH + a_c8) * 2,
                       Bt + (size_t)(col0 + row) * K + k0 + a_c8);
        }
        CP_COMMIT();
    }

    for (int ch = 0; ch < nch; ch++) {
        if (ch + 1 < nch) { CP_WAIT(1); } else { CP_WAIT(0); }
        __syncthreads();   // stage (ch+2)%STG last read at iter ch-1 -> safe to refill

        if (ch + 2 < nch) {
            int k0 = (ch + 2) * BK;
            int nb = (ch + 2) % STG;
            uint32_t baseA = sbase + (uint32_t)(nb * STAGE_BYTES);
            uint32_t baseB = baseA + A_BYTES;
#pragma unroll
            for (int v = 0; v < 2; v++) {
                int row = a_row0 + v * 64;
                CP_ASYNC16(baseA + (uint32_t)(row * PITCH + a_c8) * 2,
                           A + (size_t)(row0 + row) * K + k0 + a_c8);
                CP_ASYNC16(baseB + (uint32_t)(row * PITCH + a_c8) * 2,
                           Bt + (size_t)(col0 + row) * K + k0 + a_c8);
            }
            CP_COMMIT();
        }

        int buf = ch % STG;
        uint32_t aBase = sbase + (uint32_t)(buf * STAGE_BYTES);
        uint32_t bBase = aBase + A_BYTES;

#pragma unroll
        for (int kk = 0; kk < 4; kk++) {
            uint32_t a[2][4], b[4][2];
#pragma unroll
            for (int i = 0; i < 2; i++) {
                int r = warp_m * 32 + i * 16 + (lane & 15);
                int c = kk * 16 + ((lane >> 4) << 3);
                uint32_t addr = aBase + (uint32_t)(r * PITCH + c) * 2;
                asm volatile("ldmatrix.sync.aligned.m8n8.x4.shared.b16 {%0,%1,%2,%3}, [%4];"
                             : "=r"(a[i][0]), "=r"(a[i][1]), "=r"(a[i][2]), "=r"(a[i][3])
                             : "r"(addr));
            }
#pragma unroll
            for (int j = 0; j < 4; j++) {
                int r = warp_n * 32 + j * 8 + (lane & 7);
                int c = kk * 16 + (((lane >> 3) & 1) << 3);
                uint32_t addr = bBase + (uint32_t)(r * PITCH + c) * 2;
                asm volatile("ldmatrix.sync.aligned.m8n8.x2.shared.b16 {%0,%1}, [%2];"
                             : "=r"(b[j][0]), "=r"(b[j][1]) : "r"(addr));
            }
#pragma unroll
            for (int i = 0; i < 2; i++)
#pragma unroll
                for (int j = 0; j < 4; j++) {
                    asm volatile(
                        "mma.sync.aligned.m16n8k16.row.col.f32.bf16.bf16.f32 "
                        "{%0,%1,%2,%3}, {%4,%5,%6,%7}, {%8,%9}, {%0,%1,%2,%3};"
                        : "+f"(acc[i][j][0]), "+f"(acc[i][j][1]),
                          "+f"(acc[i][j][2]), "+f"(acc[i][j][3])
                        : "r"(a[i][0]), "r"(a[i][1]), "r"(a[i][2]), "r"(a[i][3]),
                          "r"(b[j][0]), "r"(b[j][1]));
                }
        }
    }

    // direct-fragment epilogue
    const int qr = lane >> 2;
    const int qc = (lane & 3) * 2;
#pragma unroll
    for (int i = 0; i < 2; i++) {
#pragma unroll
        for (int j = 0; j < 4; j++) {
            int gc = col0 + warp_n * 32 + j * 8 + qc;
#pragma unroll
            for (int half = 0; half < 2; half++) {
                int gr = row0 + warp_m * 32 + i * 16 + qr + half * 8;
                float v0 = acc[i][j][half * 2 + 0];
                float v1 = acc[i][j][half * 2 + 1];
                if (flags & GF_BIAS) { v0 += bias[gc]; v1 += bias[gc + 1]; }
                if (flags & GF_RES) {
                    const float* rp = res + (size_t)gr * N + gc;
                    v0 += rp[0]; v1 += rp[1];
                }
                if (flags & GF_RELU) { v0 = fmaxf(v0, 0.f); v1 = fmaxf(v1, 0.f); }
                if (outf) *(float2*)(outf + (size_t)gr * N + gc) = make_float2(v0, v1);
                if (outb) {
                    __nv_bfloat162 p = __floats2bfloat162_rn(v0, v1);
                    *(__nv_bfloat162*)(outb + (size_t)gr * N + gc) = p;
                }
            }
        }
    }
}

// ---------------- flash attention, double-buffered cp.async K/V ----------------
#define APITCH 24

__global__ __launch_bounds__(128) void fattn_kernel(
    const __nv_bfloat16* __restrict__ qkv, __nv_bfloat16* __restrict__ out)
{
    __shared__ __align__(16) __nv_bfloat16 Qs[64 * APITCH];
    __shared__ __align__(16) __nv_bfloat16 Ks[2][64 * APITCH];
    __shared__ __align__(16) __nv_bfloat16 Vs[2][64 * APITCH];

    const int qb = blockIdx.x;
    const int b  = blockIdx.y >> 4;
    const int h  = blockIdx.y & 15;
    const int tid = threadIdx.x, wm = tid >> 5, lane = tid & 31;
    const int g = lane >> 2, tig = lane & 3;
    const int LD = 3 * C_;
    const size_t base = (size_t)b * T_ * LD;

    const int l_row = tid >> 1, l_half = tid & 1;

    {
        const __nv_bfloat16* src = qkv + base + (size_t)(qb * 64 + l_row) * LD + h * D_ + l_half * 8;
        uint4 u = *(const uint4*)src;
        __nv_bfloat16 tmp[8]; *(uint4*)&tmp[0] = u;
#pragma unroll
        for (int i = 0; i < 8; i++)
            Qs[l_row * APITCH + l_half * 8 + i] =
                __float2bfloat16(__bfloat162float(tmp[i]) * QSCALE_);
        const uint4 ones_vec = make_uint4(0x00003F80u, 0u, 0u, 0u);
        *(uint4*)&Vs[l_half][l_row * APITCH + 16] = ones_vec;
    }

    {
        const __nv_bfloat16* ksrc = qkv + base + (size_t)l_row * LD + C_ + h * D_ + l_half * 8;
        CP_ASYNC16(smem_u32(&Ks[0][l_row * APITCH + l_half * 8]), ksrc);
        CP_ASYNC16(smem_u32(&Vs[0][l_row * APITCH + l_half * 8]), ksrc + C_);
        CP_COMMIT();
    }
    __syncthreads();

    uint32_t qa[4];
    {
        int r = wm * 16 + (lane & 15);
        int c = (lane >> 4) << 3;
        uint32_t addr = smem_u32(&Qs[r * APITCH + c]);
        asm volatile("ldmatrix.sync.aligned.m8n8.x4.shared.b16 {%0,%1,%2,%3}, [%4];"
                     : "=r"(qa[0]), "=r"(qa[1]), "=r"(qa[2]), "=r"(qa[3]) : "r"(addr));
    }

    float o[3][4];
#pragma unroll
    for (int n = 0; n < 3; n++)
#pragma unroll
        for (int r = 0; r < 4; r++) o[n][r] = 0.f;

    for (int kt = 0; kt <= qb; kt++) {
        CP_WAIT(0);
        __syncthreads();

        if (kt < qb) {
            const __nv_bfloat16* ksrc = qkv + base + (size_t)((kt + 1) * 64 + l_row) * LD + C_ + h * D_ + l_half * 8;
            int nb = (kt + 1) & 1;
            CP_ASYNC16(smem_u32(&Ks[nb][l_row * APITCH + l_half * 8]), ksrc);
            CP_ASYNC16(smem_u32(&Vs[nb][l_row * APITCH + l_half * 8]), ksrc + C_);
            CP_COMMIT();
        }

        const __nv_bfloat16* Kb = Ks[kt & 1];
        const __nv_bfloat16* Vb = Vs[kt & 1];

        float s[8][4];
#pragma unroll
        for (int f = 0; f < 8; f++) {
            uint32_t b0, b1;
            int r = f * 8 + (lane & 7);
            int c = ((lane >> 3) & 1) << 3;
            uint32_t addr = smem_u32(&Kb[r * APITCH + c]);
            asm volatile("ldmatrix.sync.aligned.m8n8.x2.shared.b16 {%0,%1}, [%2];"
                         : "=r"(b0), "=r"(b1) : "r"(addr));
            s[f][0] = s[f][1] = s[f][2] = s[f][3] = 0.f;
            asm volatile(
                "mma.sync.aligned.m16n8k16.row.col.f32.bf16.bf16.f32 "
                "{%0,%1,%2,%3}, {%4,%5,%6,%7}, {%8,%9}, {%0,%1,%2,%3};"
                : "+f"(s[f][0]), "+f"(s[f][1]), "+f"(s[f][2]), "+f"(s[f][3])
                : "r"(qa[0]), "r"(qa[1]), "r"(qa[2]), "r"(qa[3]), "r"(b0), "r"(b1));
        }

        if (kt == qb) {
            int q0 = wm * 16 + g, q1 = q0 + 8;
#pragma unroll
            for (int f = 0; f < 8; f++) {
                int k0 = f * 8 + 2 * tig;
                if (k0     > q0) s[f][0] = -1e30f;
                if (k0 + 1 > q0) s[f][1] = -1e30f;
                if (k0     > q1) s[f][2] = -1e30f;
                if (k0 + 1 > q1) s[f][3] = -1e30f;
            }
        }

        uint32_t pa[8][2];
#pragma unroll
        for (int f = 0; f < 8; f++) {
            float p0 = ex2f(s[f][0]), p1 = ex2f(s[f][1]);
            float p2 = ex2f(s[f][2]), p3 = ex2f(s[f][3]);
            __nv_bfloat162 u = __floats2bfloat162_rn(p0, p1);
            __nv_bfloat162 w = __floats2bfloat162_rn(p2, p3);
            pa[f][0] = *(uint32_t*)&u;
            pa[f][1] = *(uint32_t*)&w;
        }

#pragma unroll
        for (int j2 = 0; j2 < 4; j2++) {
            int vr = j2 * 16 + (lane & 15);
#pragma unroll
            for (int n = 0; n < 3; n++) {
                uint32_t b0, b1;
                uint32_t addr = smem_u32(&Vb[vr * APITCH + n * 8]);
                asm volatile("ldmatrix.sync.aligned.m8n8.x2.trans.shared.b16 {%0,%1}, [%2];"
                             : "=r"(b0), "=r"(b1) : "r"(addr));
                asm volatile(
                    "mma.sync.aligned.m16n8k16.row.col.f32.bf16.bf16.f32 "
                    "{%0,%1,%2,%3}, {%4,%5,%6,%7}, {%8,%9}, {%0,%1,%2,%3};"
                    : "+f"(o[n][0]), "+f"(o[n][1]), "+f"(o[n][2]), "+f"(o[n][3])
                    : "r"(pa[2*j2][0]), "r"(pa[2*j2][1]),
                      "r"(pa[2*j2+1][0]), "r"(pa[2*j2+1][1]),
                      "r"(b0), "r"(b1));
            }
        }
    }

    float l0 = __shfl_sync(0xffffffffu, o[2][0], lane & ~3);
    float l1 = __shfl_sync(0xffffffffu, o[2][2], lane & ~3);
    float inv0 = 1.f / l0, inv1 = 1.f / l1;

    int gr0 = qb * 64 + wm * 16 + g;
    int gr1 = gr0 + 8;
#pragma unroll
    for (int n = 0; n < 2; n++) {
        int gc = h * D_ + n * 8 + 2 * tig;
        __nv_bfloat162 p0 = __floats2bfloat162_rn(o[n][0] * inv0, o[n][1] * inv0);
        __nv_bfloat162 p1 = __floats2bfloat162_rn(o[n][2] * inv1, o[n][3] * inv1);
        *(__nv_bfloat162*)(out + (size_t)(b * T_ + gr0) * C_ + gc) = p0;
        *(__nv_bfloat162*)(out + (size_t)(b * T_ + gr1) * C_ + gc) = p1;
    }
}

// ---------------- host ----------------
extern "C" void kernel_launch(void* const* d_in, const int* in_sizes, int n_in,
                              void* d_out, int out_size)
{
    const float* x   = (const float*)d_in[0];
    const float* Wq  = (const float*)d_in[1];
    const float* Wk  = (const float*)d_in[2];
    const float* Wv  = (const float*)d_in[3];
    const float* Wp  = (const float*)d_in[4];
    const float* bp  = (const float*)d_in[5];
    const float* W1  = (const float*)d_in[6];
    const float* b1  = (const float*)d_in[7];
    const float* W2  = (const float*)d_in[8];
    const float* b2  = (const float*)d_in[9];
    const float* g1  = (const float*)d_in[10];
    const float* be1 = (const float*)d_in[11];
    const float* g2  = (const float*)d_in[12];
    const float* be2 = (const float*)d_in[13];
    float* out = (float*)d_out;

    __nv_bfloat16 *h1b, *attb, *h2b, *h3b, *qkvb, *wqkvt, *wpt, *w1t, *w2t;
    float *x2;
    cudaGetSymbolAddress((void**)&h1b,   g_h1b);
    cudaGetSymbolAddress((void**)&attb,  g_attb);
    cudaGetSymbolAddress((void**)&h2b,   g_h2b);
    cudaGetSymbolAddress((void**)&h3b,   g_h3b);
    cudaGetSymbolAddress((void**)&qkvb,  g_qkvb);
    cudaGetSymbolAddress((void**)&x2,    g_x2);
    cudaGetSymbolAddress((void**)&wqkvt, g_wqkvt);
    cudaGetSymbolAddress((void**)&wpt,   g_wpt);
    cudaGetSymbolAddress((void**)&w1t,   g_w1t);
    cudaGetSymbolAddress((void**)&w2t,   g_w2t);

    cudaFuncSetAttribute(mma_gemm, cudaFuncAttributeMaxDynamicSharedMemorySize, GEMM_DSM);

    // prep: weight transposes + ln1 in one launch
    prep_kernel<<<768 + M_/8, 256>>>(Wq, Wk, Wv, Wp, W1, W2,
                                     wqkvt, wpt, w1t, w2t,
                                     x, g1, be1, h1b);

    // qkv = h1 @ [Wq|Wk|Wv] (bf16 out)
    mma_gemm<<<dim3(6, M_/BM), 512, GEMM_DSM>>>(h1b, wqkvt, nullptr, nullptr,
                                                nullptr, qkvb, 3*C_, C_, 0);
    // flash attention -> attb bf16
    fattn_kernel<<<dim3(T_/64, B_*H_), 128>>>(qkvb, attb);

    // x2 = x + attb @ Wp^T + bp
    mma_gemm<<<dim3(2, M_/BM), 512, GEMM_DSM>>>(attb, wpt, bp, x,
                                                x2, nullptr, C_, C_, GF_BIAS | GF_RES);
    // ln2 -> h2 bf16
    ln_kernel<<<M_/8, 256>>>(x2, g2, be2, h2b);

    // h3 = relu(h2 @ W1^T + b1)
    mma_gemm<<<dim3(8, M_/BM), 512, GEMM_DSM>>>(h2b, w1t, b1, nullptr,
                                                nullptr, h3b, FF_, C_, GF_BIAS | GF_RELU);
    // out = x2 + h3 @ W2^T + b2
    mma_gemm<<<dim3(2, M_/BM), 512, GEMM_DSM>>>(h3b, w2t, b2, x2,
                                                out, nullptr, C_, FF_, GF_BIAS | GF_RES);
}